// round 11
// baseline (speedup 1.0000x reference)
#include <cuda_runtime.h>
#include <cstdint>

// ---------------------------------------------------------------------------
// QuantumNeuralNetwork: fused MLP + 4-qubit expval + classifier
//
// <Z0> = e^T M e with M = Re(U' Z0 U) precomputed by build_M_kernel.
//
// R10: explicit 1-deep software pipeline in both GEMM k-loops (prefetch k+1
// operands during k's FMAs, uniform across unroll seams). Boundary guard
// elided: the final prefetch reads in-bounds padding and is discarded.
// __launch_bounds__(128,4) pins 4 blocks/SM.
// ---------------------------------------------------------------------------

#define XRS 49   // image tile row stride (floats), odd -> conflict-free LDS.32
#define XTS 17   // text  tile row stride

#define OFF_WI1A   0                        // [48][32] cols 0-31
#define OFF_WI1B   (48*32 + 4)              // [48][32] cols 32-63, +16B skew
#define OFF_XRI    (OFF_WI1B + 48*32 + 4)   // [128][XRS] image tile row-major
#define OFF_XRT    (OFF_XRI + 128*XRS)      // [128][XTS] text tile row-major
#define OFF_WT1    (OFF_XRT + 128*XTS)      // [16][32]
#define OFF_WI2    (OFF_WT1 + 512)          // [64][4] natural iW2
#define OFF_WT2    (OFF_WI2 + 256)          // [32][4] natural tW2
#define OFF_IB1    (OFF_WT2 + 128)          // [64]
#define OFF_TB1    (OFF_IB1 + 64)           // [32]
#define OFF_B2     (OFF_TB1 + 32)           // [4]
#define OFF_MS     (OFF_B2 + 4)             // [16][16]
#define OFF_CLS    (OFF_MS + 256)           // cW1[16] cb1[16] cW2[32] cb2[2]
#define SMEM_FLOATS (OFF_CLS + 68)

typedef unsigned long long ull;

#define FFMA2(d, a, b) \
    asm("fma.rn.f32x2 %0, %1, %2, %0;" : "+l"(d) : "l"(a), "l"(b))
#define MUL2(d, a, b) \
    asm("mul.rn.f32x2 %0, %1, %2;" : "=l"(d) : "l"(a), "l"(b))
#define ADD2(d, a, b) \
    asm("add.rn.f32x2 %0, %1, %2;" : "=l"(d) : "l"(a), "l"(b))
#define PACK2(out, lo, hi) \
    asm("mov.b64 %0, {%1, %2};" : "=l"(out) : "r"(__float_as_uint(lo)), "r"(__float_as_uint(hi)))
#define UNPACK2(lo, hi, v) do { unsigned _ulo, _uhi; \
    asm("mov.b64 {%0, %1}, %2;" : "=r"(_ulo), "=r"(_uhi) : "l"(v)); \
    lo = __uint_as_float(_ulo); hi = __uint_as_float(_uhi); } while (0)

__device__ __align__(16) float g_M[256];

// ---------------------------------------------------------------------------
// Prologue: build M[16][16] = Re(U^dagger Z0 U) from qweights [2][4][3].
// ---------------------------------------------------------------------------
__global__ void build_M_kernel(const float* __restrict__ qw) {
    __shared__ float Ure[16][16], Uim[16][16];
    const int k = threadIdx.x;  // column index 0..15
    float vr[16], vi[16];
#pragma unroll
    for (int n = 0; n < 16; n++) { vr[n] = (n == k) ? 1.f : 0.f; vi[n] = 0.f; }

    for (int l = 0; l < 2; l++) {
        for (int i = 0; i < 4; i++) {
            float phi = qw[(l*4 + i)*3 + 0];
            float th  = qw[(l*4 + i)*3 + 1];
            float om  = qw[(l*4 + i)*3 + 2];
            float ct = cosf(0.5f*th), st = sinf(0.5f*th);
            float sp, cp, sm, cm;
            sincosf(0.5f*(phi + om), &sp, &cp);
            sincosf(0.5f*(phi - om), &sm, &cm);
            float u00r =  cp*ct, u00i = -sp*ct;
            float u01r = -cm*st, u01i = -sm*st;
            float u10r =  cm*st, u10i = -sm*st;
            float u11r =  cp*ct, u11i =  sp*ct;
            int mask = 1 << (3 - i);
#pragma unroll
            for (int n = 0; n < 16; n++) {
                if (n & mask) continue;
                int n1 = n | mask;
                float r0 = vr[n],  i0 = vi[n];
                float r1 = vr[n1], i1 = vi[n1];
                vr[n]  = u00r*r0 - u00i*i0 + u01r*r1 - u01i*i1;
                vi[n]  = u00r*i0 + u00i*r0 + u01r*i1 + u01i*r1;
                vr[n1] = u10r*r0 - u10i*i0 + u11r*r1 - u11i*i1;
                vi[n1] = u10r*i0 + u10i*r0 + u11r*i1 + u11i*r1;
            }
        }
        for (int i = 0; i < 3; i++) {
            int m1 = 1 << (3 - i), m2 = 1 << (2 - i);
#pragma unroll
            for (int n = 0; n < 16; n++)
                if ((n & m1) && (n & m2)) { vr[n] = -vr[n]; vi[n] = -vi[n]; }
        }
    }
#pragma unroll
    for (int n = 0; n < 16; n++) { Ure[n][k] = vr[n]; Uim[n][k] = vi[n]; }
    __syncthreads();
#pragma unroll
    for (int j = 0; j < 16; j++) {
        float acc = 0.f;
#pragma unroll
        for (int b = 0; b < 16; b++) {
            float z = (b & 8) ? -1.f : 1.f;
            acc += z * (Ure[b][j]*Ure[b][k] + Uim[b][j]*Uim[b][k]);
        }
        g_M[j*16 + k] = acc;
    }
}

// ---------------------------------------------------------------------------
// Main fused kernel: 128 threads handle 128 samples per block.
// ---------------------------------------------------------------------------
__global__ __launch_bounds__(128, 4) void qnn_kernel(
    const float* __restrict__ text, const float* __restrict__ image,
    const float* __restrict__ tW1,  const float* __restrict__ tb1,
    const float* __restrict__ tW2,  const float* __restrict__ tb2,
    const float* __restrict__ iW1,  const float* __restrict__ ib1,
    const float* __restrict__ iW2,  const float* __restrict__ ib2,
    const float* __restrict__ cW1,  const float* __restrict__ cb1,
    const float* __restrict__ cW2,  const float* __restrict__ cb2,
    float* __restrict__ out)
{
    extern __shared__ __align__(128) float smf[];
    float* wI1a = smf + OFF_WI1A;
    float* wI1b = smf + OFF_WI1B;
    float* xRi  = smf + OFF_XRI;
    float* xRt  = smf + OFF_XRT;
    float* wT1s = smf + OFF_WT1;
    float* wI2s = smf + OFF_WI2;   // [64][4] natural layout
    float* wT2s = smf + OFF_WT2;   // [32][4] natural layout
    float* ib1s = smf + OFF_IB1;
    float* tb1s = smf + OFF_TB1;
    float* b2s  = smf + OFF_B2;
    float* Ms   = smf + OFF_MS;
    float* cls  = smf + OFF_CLS;
    float* feats = xRi;            // aliased after GEMMs: [128][4]

    const int tid = threadIdx.x;
    const size_t base = (size_t)blockIdx.x * 128;

    // ---- stage inputs + weights into shared ----
    {
        const float4* ig = (const float4*)(image + base * 48);
#pragma unroll
        for (int it = 0; it < 12; it++) {
            int idx = it*128 + tid;
            float4 v = ig[idx];
            int s  = idx / 12;
            int kq = idx - s*12;
            float* p = &xRi[s*XRS + 4*kq];
            p[0] = v.x; p[1] = v.y; p[2] = v.z; p[3] = v.w;
        }
        const float4* tg = (const float4*)(text + base * 16);
#pragma unroll
        for (int it = 0; it < 4; it++) {
            int idx = it*128 + tid;
            float4 v = tg[idx];
            int s  = idx >> 2;
            int kq = idx & 3;
            float* p = &xRt[s*XTS + 4*kq];
            p[0] = v.x; p[1] = v.y; p[2] = v.z; p[3] = v.w;
        }
        // iW1 [48][64] -> split halves with 16B-skewed second half
#pragma unroll
        for (int it = 0; it < 6; it++) {
            int idx = it*128 + tid;            // float4 index 0..767
            float4 v = ((const float4*)iW1)[idx];
            int kk = idx >> 4;                 // row 0..47
            int nb = idx & 15;                 // block-of-4 within row
            float* dst = (nb < 8) ? &wI1a[kk*32 + nb*4]
                                  : &wI1b[kk*32 + (nb-8)*4];
            *(float4*)dst = v;
        }
        ((float4*)wT1s)[tid] = ((const float4*)tW1)[tid];
        if (tid < 64) {
            ((float4*)wI2s)[tid] = ((const float4*)iW2)[tid];  // natural [64][4]
            ib1s[tid] = ib1[tid];
            ((float4*)Ms)[tid] = ((const float4*)g_M)[tid];
        }
        if (tid < 32) {
            ((float4*)wT2s)[tid] = ((const float4*)tW2)[tid];  // natural [32][4]
            tb1s[tid] = tb1[tid];
        }
        if (tid < 16) {
            cls[tid] = cW1[tid]; cls[16+tid] = cb1[tid];
            cls[32+2*tid] = cW2[2*tid]; cls[33+2*tid] = cW2[2*tid+1];
        }
        if (tid < 4) b2s[tid] = ib2[tid] + tb2[tid];
        if (tid < 2) cls[64+tid] = cb2[tid];
    }
    __syncthreads();

    const int trow = tid >> 3;        // 0..15 : sample group
    const int tcol = tid & 7;         // 0..7  : neuron group
    const int m0 = trow * 8;

    // ---- image MLP1: 128x64, K=48, microtile 8x8, packed f32x2 over n ----
    // software-pipelined: prefetch k+1 while doing k's FMAs.
    const int n0 = tcol * 8;
    const float* wb = (tcol < 4) ? (wI1a + n0) : (wI1b + (n0 - 32));
    const float* xb = xRi + m0 * XRS;

    ull acc[8][4];
    {
        ulonglong2 bb0 = *(const ulonglong2*)&ib1s[n0];
        ulonglong2 bb1 = *(const ulonglong2*)&ib1s[n0 + 4];
#pragma unroll
        for (int i = 0; i < 8; i++) {
            acc[i][0] = bb0.x; acc[i][1] = bb0.y;
            acc[i][2] = bb1.x; acc[i][3] = bb1.y;
        }
    }

    {
        float a_c[8]; ulonglong2 bA_c, bB_c;
#pragma unroll
        for (int i = 0; i < 8; i++) a_c[i] = xb[i*XRS];
        bA_c = *(const ulonglong2*)&wb[0];
        bB_c = *(const ulonglong2*)&wb[4];

#pragma unroll 8
        for (int k = 0; k < 48; k++) {
            // prefetch k+1 (k=47 prefetch reads in-bounds padding; unused)
            float a_n[8];
#pragma unroll
            for (int i = 0; i < 8; i++) a_n[i] = xb[i*XRS + k + 1];
            ulonglong2 bA_n = *(const ulonglong2*)&wb[(k+1)*32];
            ulonglong2 bB_n = *(const ulonglong2*)&wb[(k+1)*32 + 4];

#pragma unroll
            for (int i = 0; i < 8; i++) {
                ull aa; PACK2(aa, a_c[i], a_c[i]);
                FFMA2(acc[i][0], aa, bA_c.x);
                FFMA2(acc[i][1], aa, bA_c.y);
                FFMA2(acc[i][2], aa, bB_c.x);
                FFMA2(acc[i][3], aa, bB_c.y);
            }
#pragma unroll
            for (int i = 0; i < 8; i++) a_c[i] = a_n[i];
            bA_c = bA_n; bB_c = bB_n;
        }
    }

    // ---- fold into imf partials: relu(h)·iW2, packed over the 4 outputs ----
    ull pv[8][2];
#pragma unroll
    for (int i = 0; i < 8; i++) { pv[i][0] = 0ull; pv[i][1] = 0ull; }

#pragma unroll
    for (int jj = 0; jj < 4; jj++) {     // j = 2jj, 2jj+1
        int nj0 = n0 + 2*jj;
        ulonglong2 wA = *(const ulonglong2*)&wI2s[nj0*4];
        ulonglong2 wB = *(const ulonglong2*)&wI2s[(nj0+1)*4];
#pragma unroll
        for (int i = 0; i < 8; i++) {
            float h0, h1;
            UNPACK2(h0, h1, acc[i][jj]);
            h0 = fmaxf(h0, 0.f); h1 = fmaxf(h1, 0.f);
            ull hh0, hh1; PACK2(hh0, h0, h0); PACK2(hh1, h1, h1);
            FFMA2(pv[i][0], hh0, wA.x);
            FFMA2(pv[i][1], hh0, wA.y);
            FFMA2(pv[i][0], hh1, wB.x);
            FFMA2(pv[i][1], hh1, wB.y);
        }
    }

    // ---- text MLP1: 128x32, K=16, microtile 8x4, packed + pipelined ----
    const int t0 = tcol * 4;
    const float* xt = xRt + m0 * XTS;
    ull acc2[8][2];
    {
        ulonglong2 bb = *(const ulonglong2*)&tb1s[t0];
#pragma unroll
        for (int i = 0; i < 8; i++) { acc2[i][0] = bb.x; acc2[i][1] = bb.y; }
    }

    {
        float a_c[8]; ulonglong2 b_c;
#pragma unroll
        for (int i = 0; i < 8; i++) a_c[i] = xt[i*XTS];
        b_c = *(const ulonglong2*)&wT1s[t0];

#pragma unroll 8
        for (int k = 0; k < 16; k++) {
            float a_n[8];
#pragma unroll
            for (int i = 0; i < 8; i++) a_n[i] = xt[i*XTS + k + 1];
            ulonglong2 b_n = *(const ulonglong2*)&wT1s[(k+1)*32 + t0];

#pragma unroll
            for (int i = 0; i < 8; i++) {
                ull aa; PACK2(aa, a_c[i], a_c[i]);
                FFMA2(acc2[i][0], aa, b_c.x);
                FFMA2(acc2[i][1], aa, b_c.y);
            }
#pragma unroll
            for (int i = 0; i < 8; i++) a_c[i] = a_n[i];
            b_c = b_n;
        }
    }

#pragma unroll
    for (int jj = 0; jj < 2; jj++) {     // j = 2jj, 2jj+1
        int nj0 = t0 + 2*jj;
        ulonglong2 wA = *(const ulonglong2*)&wT2s[nj0*4];
        ulonglong2 wB = *(const ulonglong2*)&wT2s[(nj0+1)*4];
#pragma unroll
        for (int i = 0; i < 8; i++) {
            float h0, h1;
            UNPACK2(h0, h1, acc2[i][jj]);
            h0 = fmaxf(h0, 0.f); h1 = fmaxf(h1, 0.f);
            ull hh0, hh1; PACK2(hh0, h0, h0); PACK2(hh1, h1, h1);
            FFMA2(pv[i][0], hh0, wA.x);
            FFMA2(pv[i][1], hh0, wA.y);
            FFMA2(pv[i][0], hh1, wB.x);
            FFMA2(pv[i][1], hh1, wB.y);
        }
    }

    // ---- reduce partials across the 8 neuron-group lanes ----
#pragma unroll
    for (int i = 0; i < 8; i++)
#pragma unroll
        for (int n = 0; n < 2; n++) {
            ull v = pv[i][n];
            ull t;
            t = __shfl_xor_sync(0xffffffffu, v, 4); ADD2(v, v, t);
            t = __shfl_xor_sync(0xffffffffu, v, 2); ADD2(v, v, t);
            t = __shfl_xor_sync(0xffffffffu, v, 1); ADD2(v, v, t);
            pv[i][n] = v;
        }

    __syncthreads();   // everyone done reading xRi/xRt before feats alias write
    if (tcol == 0) {
        ulonglong2 bb = *(const ulonglong2*)b2s;
        ull half2p; PACK2(half2p, 0.5f, 0.5f);
#pragma unroll
        for (int i = 0; i < 8; i++) {
            ull s0, s1;
            ADD2(s0, pv[i][0], bb.x);
            ADD2(s1, pv[i][1], bb.y);
            MUL2(s0, s0, half2p);
            MUL2(s1, s1, half2p);
            ulonglong2 fo; fo.x = s0; fo.y = s1;
            *(ulonglong2*)&feats[(m0 + i) * 4] = fo;
        }
    }
    __syncthreads();

    // ---- quantum expval + classifier: one sample per thread ----
    float4 f = *(const float4*)&feats[tid * 4];
    float c0, q0s, c1, q1s, c2, q2s, c3, q3s;
    __sincosf(0.5f*f.x, &q0s, &c0);
    __sincosf(0.5f*f.y, &q1s, &c1);
    __sincosf(0.5f*f.z, &q2s, &c2);
    __sincosf(0.5f*f.w, &q3s, &c3);

    float p01[4] = {c0*c1, c0*q1s, q0s*c1, q0s*q1s};
    float p23[4] = {c2*c3, c2*q3s, q2s*c3, q2s*q3s};

    ull p23p0, p23p1;
    PACK2(p23p0, p23[0], p23[1]);
    PACK2(p23p1, p23[2], p23[3]);
    ull e2[8];
    float e[16];
#pragma unroll
    for (int a = 0; a < 4; a++) {
        ull pa; PACK2(pa, p01[a], p01[a]);
        MUL2(e2[a*2+0], pa, p23p0);
        MUL2(e2[a*2+1], pa, p23p1);
        UNPACK2(e[a*4+0], e[a*4+1], e2[a*2+0]);
        UNPACK2(e[a*4+2], e[a*4+3], e2[a*2+1]);
    }

    float q = 0.f;
#pragma unroll
    for (int j = 0; j < 16; j++) {
        const ulonglong2* Mr = (const ulonglong2*)&Ms[j*16];
        ulonglong2 m0v = Mr[0], m1v = Mr[1], m2v = Mr[2], m3v = Mr[3];
        ull t2 = 0ull;
        FFMA2(t2, m0v.x, e2[0]); FFMA2(t2, m0v.y, e2[1]);
        FFMA2(t2, m1v.x, e2[2]); FFMA2(t2, m1v.y, e2[3]);
        FFMA2(t2, m2v.x, e2[4]); FFMA2(t2, m2v.y, e2[5]);
        FFMA2(t2, m3v.x, e2[6]); FFMA2(t2, m3v.y, e2[7]);
        float tl, th; UNPACK2(tl, th, t2);
        q = fmaf(e[j], tl + th, q);
    }

    float o0 = cls[64], o1 = cls[65];
#pragma unroll
    for (int m = 0; m < 16; m++) {
        float h = fmaxf(fmaf(q, cls[m], cls[16+m]), 0.f);
        o0 = fmaf(h, cls[32+2*m], o0);
        o1 = fmaf(h, cls[33+2*m], o1);
    }
    float2 res; res.x = o0; res.y = o1;
    ((float2*)out)[base + tid] = res;
}

// ---------------------------------------------------------------------------
extern "C" void kernel_launch(void* const* d_in, const int* in_sizes, int n_in,
                              void* d_out, int out_size) {
    const float* text = (const float*)d_in[0];
    const float* image= (const float*)d_in[1];
    const float* tW1  = (const float*)d_in[2];
    const float* tb1  = (const float*)d_in[3];
    const float* tW2  = (const float*)d_in[4];
    const float* tb2  = (const float*)d_in[5];
    const float* iW1  = (const float*)d_in[6];
    const float* ib1  = (const float*)d_in[7];
    const float* iW2  = (const float*)d_in[8];
    const float* ib2  = (const float*)d_in[9];
    const float* qw   = (const float*)d_in[10];
    const float* cW1  = (const float*)d_in[11];
    const float* cb1  = (const float*)d_in[12];
    const float* cW2  = (const float*)d_in[13];
    const float* cb2  = (const float*)d_in[14];
    float* out = (float*)d_out;

    const int B = in_sizes[0] / 16;
    const int grid = B / 128;
    const size_t smem = SMEM_FLOATS * sizeof(float);

    cudaFuncSetAttribute(qnn_kernel, cudaFuncAttributeMaxDynamicSharedMemorySize, (int)smem);

    build_M_kernel<<<1, 16>>>(qw);
    qnn_kernel<<<grid, 128, smem>>>(text, image, tW1, tb1, tW2, tb2,
                                    iW1, ib1, iW2, ib2,
                                    cW1, cb1, cW2, cb2, out);
}

// round 13
// speedup vs baseline: 1.2046x; 1.2046x over previous
#include <cuda_runtime.h>
#include <cstdint>

// ---------------------------------------------------------------------------
// QuantumNeuralNetwork: mma.sync bf16-split image GEMM + FFMA2 text GEMM
//
// <Z0> = e^T M e with M = Re(U' Z0 U) precomputed by build_M_kernel.
//
// R12: tcgen05 is compile-blocked (harness targets compute_103, no 'a'
// features). Use warp-level mma.sync.m16n8k16 (sm_80+, compiles) instead.
// Image MLP1 as bf16 3-term split (hh + hl + lh, ll dropped ~2^-18).
// ldmatrix with 112B row stride -> conflict-free operand loads. D fragments
// folded (relu . iW2) in registers, quad-shfl reduced, merged with the R9
// FFMA2 text path through two small smem buffers aliased over dead tiles.
// ---------------------------------------------------------------------------

typedef unsigned long long ull;

#define FFMA2(d, a, b) \
    asm("fma.rn.f32x2 %0, %1, %2, %0;" : "+l"(d) : "l"(a), "l"(b))
#define MUL2(d, a, b) \
    asm("mul.rn.f32x2 %0, %1, %2;" : "=l"(d) : "l"(a), "l"(b))
#define ADD2(d, a, b) \
    asm("add.rn.f32x2 %0, %1, %2;" : "=l"(d) : "l"(a), "l"(b))
#define PACK2(out, lo, hi) \
    asm("mov.b64 %0, {%1, %2};" : "=l"(out) : "r"(__float_as_uint(lo)), "r"(__float_as_uint(hi)))
#define UNPACK2(lo, hi, v) do { unsigned _ulo, _uhi; \
    asm("mov.b64 {%0, %1}, %2;" : "=r"(_ulo), "=r"(_uhi) : "l"(v)); \
    lo = __uint_as_float(_ulo); hi = __uint_as_float(_uhi); } while (0)

// ---- smem byte offsets ----
#define SM_AHI   0                      // image A hi: 128 rows x 112B (48 bf16 + pad)
#define SM_ALO   14336
#define SM_BHI   28672                  // image B (iW1^T) hi: 64 rows x 112B
#define SM_BLO   35840                  // (A/B region ends 43008)
#define SM_TFI   14336                  // alias over ALO after MMA: [128] float4
#define SM_TFT   16384                  // alias: [128] float4 (text sums)
#define SM_XRT   43008                  // text tile fp32 [128][17]
#define SM_WT1   51712                  // tW1 fp32 [16][32]
#define SM_EP    53760                  // epilogue consts (floats)
#define EP_WI2   0                      // [64][4]
#define EP_WT2   256                    // [32][4]
#define EP_IB1   384                    // [64]
#define EP_TB1   448                    // [32]
#define EP_B2    480                    // [4] ib2+tb2
#define EP_M     484                    // [16][16]
#define EP_CLS   740                    // cW1[16] cb1[16] cW2[32] cb2[2]
#define EP_FLOATS 808
#define SMEM_BYTES (SM_EP + EP_FLOATS*4)   // 56992

#define ASTRIDE 112   // bytes per A/B row (48/64-col bf16 tiles, conflict-free ldmatrix)
#define XTS 17        // text tile row stride (floats)

__device__ __forceinline__ uint32_t smem_u32(const void* p) {
    uint32_t a;
    asm("{ .reg .u64 t; cvta.to.shared.u64 t, %1; cvt.u32.u64 %0, t; }" : "=r"(a) : "l"(p));
    return a;
}
__device__ __forceinline__ unsigned bf16pair(float lo, float hi) {
    unsigned r; asm("cvt.rn.bf16x2.f32 %0, %1, %2;" : "=r"(r) : "f"(hi), "f"(lo)); return r;
}
__device__ __forceinline__ unsigned short bf16s(float x) {
    unsigned short h; asm("cvt.rn.bf16.f32 %0, %1;" : "=h"(h) : "f"(x)); return h;
}
__device__ __forceinline__ void ldsm_x4(unsigned* r, uint32_t addr) {
    asm volatile("ldmatrix.sync.aligned.m8n8.x4.shared.b16 {%0,%1,%2,%3}, [%4];"
        : "=r"(r[0]), "=r"(r[1]), "=r"(r[2]), "=r"(r[3]) : "r"(addr));
}
__device__ __forceinline__ void ldsm_x2(unsigned* r, uint32_t addr) {
    asm volatile("ldmatrix.sync.aligned.m8n8.x2.shared.b16 {%0,%1}, [%2];"
        : "=r"(r[0]), "=r"(r[1]) : "r"(addr));
}
__device__ __forceinline__ void mma_bf16(float* d, const unsigned* a, const unsigned* b) {
    asm volatile("mma.sync.aligned.m16n8k16.row.col.f32.bf16.bf16.f32 "
        "{%0,%1,%2,%3}, {%4,%5,%6,%7}, {%8,%9}, {%0,%1,%2,%3};"
        : "+f"(d[0]), "+f"(d[1]), "+f"(d[2]), "+f"(d[3])
        : "r"(a[0]), "r"(a[1]), "r"(a[2]), "r"(a[3]), "r"(b[0]), "r"(b[1]));
}

__device__ __align__(16) float g_M[256];

// ---------------------------------------------------------------------------
// Prologue: build M[16][16] = Re(U^dagger Z0 U) from qweights [2][4][3].
// ---------------------------------------------------------------------------
__global__ void build_M_kernel(const float* __restrict__ qw) {
    __shared__ float Ure[16][16], Uim[16][16];
    const int k = threadIdx.x;
    float vr[16], vi[16];
#pragma unroll
    for (int n = 0; n < 16; n++) { vr[n] = (n == k) ? 1.f : 0.f; vi[n] = 0.f; }

    for (int l = 0; l < 2; l++) {
        for (int i = 0; i < 4; i++) {
            float phi = qw[(l*4 + i)*3 + 0];
            float th  = qw[(l*4 + i)*3 + 1];
            float om  = qw[(l*4 + i)*3 + 2];
            float ct = cosf(0.5f*th), st = sinf(0.5f*th);
            float sp, cp, sm, cm;
            sincosf(0.5f*(phi + om), &sp, &cp);
            sincosf(0.5f*(phi - om), &sm, &cm);
            float u00r =  cp*ct, u00i = -sp*ct;
            float u01r = -cm*st, u01i = -sm*st;
            float u10r =  cm*st, u10i = -sm*st;
            float u11r =  cp*ct, u11i =  sp*ct;
            int mask = 1 << (3 - i);
#pragma unroll
            for (int n = 0; n < 16; n++) {
                if (n & mask) continue;
                int n1 = n | mask;
                float r0 = vr[n],  i0 = vi[n];
                float r1 = vr[n1], i1 = vi[n1];
                vr[n]  = u00r*r0 - u00i*i0 + u01r*r1 - u01i*i1;
                vi[n]  = u00r*i0 + u00i*r0 + u01r*i1 + u01i*r1;
                vr[n1] = u10r*r0 - u10i*i0 + u11r*r1 - u11i*i1;
                vi[n1] = u10r*i0 + u10i*r0 + u11r*i1 + u11i*r1;
            }
        }
        for (int i = 0; i < 3; i++) {
            int m1 = 1 << (3 - i), m2 = 1 << (2 - i);
#pragma unroll
            for (int n = 0; n < 16; n++)
                if ((n & m1) && (n & m2)) { vr[n] = -vr[n]; vi[n] = -vi[n]; }
        }
    }
#pragma unroll
    for (int n = 0; n < 16; n++) { Ure[n][k] = vr[n]; Uim[n][k] = vi[n]; }
    __syncthreads();
#pragma unroll
    for (int j = 0; j < 16; j++) {
        float acc = 0.f;
#pragma unroll
        for (int b = 0; b < 16; b++) {
            float z = (b & 8) ? -1.f : 1.f;
            acc += z * (Ure[b][j]*Ure[b][k] + Uim[b][j]*Uim[b][k]);
        }
        g_M[j*16 + k] = acc;
    }
}

// ---------------------------------------------------------------------------
// Main kernel: 128 threads = 128 samples per block.
// ---------------------------------------------------------------------------
__global__ __launch_bounds__(128) void qnn_kernel(
    const float* __restrict__ text, const float* __restrict__ image,
    const float* __restrict__ tW1,  const float* __restrict__ tb1,
    const float* __restrict__ tW2,  const float* __restrict__ tb2,
    const float* __restrict__ iW1,  const float* __restrict__ ib1,
    const float* __restrict__ iW2,  const float* __restrict__ ib2,
    const float* __restrict__ cW1,  const float* __restrict__ cb1,
    const float* __restrict__ cW2,  const float* __restrict__ cb2,
    float* __restrict__ out)
{
    extern __shared__ __align__(1024) char smc[];
    const uint32_t smem_base = smem_u32(smc);
    float* ep  = (float*)(smc + SM_EP);
    float* xRt = (float*)(smc + SM_XRT);
    float* wT1s= (float*)(smc + SM_WT1);

    const int tid = threadIdx.x;
    const int w   = tid >> 5;
    const int l   = tid & 31;
    const size_t base = (size_t)blockIdx.x * 128;

    // ---- stage: convert inputs/weights ----
    {
        // image A [128][48] fp32 -> Ahi/Alo bf16, row stride 112B
        const float4* ig = (const float4*)(image + base * 48);
#pragma unroll
        for (int it = 0; it < 12; it++) {
            int idx = it*128 + tid;
            float4 v = ig[idx];
            int s  = idx / 12;
            int kq = idx - s*12;
            unsigned off = (unsigned)s*ASTRIDE + 8u*kq;
            unsigned hp0 = bf16pair(v.x, v.y);
            unsigned hp1 = bf16pair(v.z, v.w);
            float r0 = v.x - __uint_as_float(hp0 << 16);
            float r1 = v.y - __uint_as_float(hp0 & 0xffff0000u);
            float r2 = v.z - __uint_as_float(hp1 << 16);
            float r3 = v.w - __uint_as_float(hp1 & 0xffff0000u);
            unsigned lp0 = bf16pair(r0, r1);
            unsigned lp1 = bf16pair(r2, r3);
            *(ull*)(smc + SM_AHI + off) = (ull)hp0 | ((ull)hp1 << 32);
            *(ull*)(smc + SM_ALO + off) = (ull)lp0 | ((ull)lp1 << 32);
        }
        // image B: iW1[48][64] -> [n][k] bf16 hi/lo
#pragma unroll
        for (int it = 0; it < 6; it++) {
            int idx = it*128 + tid;
            float4 v = ((const float4*)iW1)[idx];
            int kk = idx >> 4;
            int n0 = (idx & 15) * 4;
            float wv[4] = {v.x, v.y, v.z, v.w};
#pragma unroll
            for (int j = 0; j < 4; j++) {
                unsigned off = (unsigned)(n0 + j)*ASTRIDE + 2u*kk;
                unsigned short h = bf16s(wv[j]);
                float lo = wv[j] - __uint_as_float(((unsigned)h) << 16);
                *(unsigned short*)(smc + SM_BHI + off) = h;
                *(unsigned short*)(smc + SM_BLO + off) = bf16s(lo);
            }
        }
        // text tile fp32 row-major stride 17
        const float4* tg = (const float4*)(text + base * 16);
#pragma unroll
        for (int it = 0; it < 4; it++) {
            int idx = it*128 + tid;
            float4 v = tg[idx];
            int s  = idx >> 2;
            int kq = idx & 3;
            float* p = &xRt[s*XTS + 4*kq];
            p[0] = v.x; p[1] = v.y; p[2] = v.z; p[3] = v.w;
        }
        ((float4*)wT1s)[tid] = ((const float4*)tW1)[tid];
        if (tid < 64) {
            ((float4*)(ep + EP_WI2))[tid] = ((const float4*)iW2)[tid];
            ep[EP_IB1 + tid] = ib1[tid];
            ((float4*)(ep + EP_M))[tid] = ((const float4*)g_M)[tid];
        }
        if (tid < 32) {
            ((float4*)(ep + EP_WT2))[tid] = ((const float4*)tW2)[tid];
            ep[EP_TB1 + tid] = tb1[tid];
        }
        if (tid < 16) {
            ep[EP_CLS + tid] = cW1[tid];
            ep[EP_CLS + 16 + tid] = cb1[tid];
            ep[EP_CLS + 32 + 2*tid] = cW2[2*tid];
            ep[EP_CLS + 33 + 2*tid] = cW2[2*tid + 1];
        }
        if (tid < 4) ep[EP_B2 + tid] = ib2[tid] + tb2[tid];
        if (tid < 2) ep[EP_CLS + 64 + tid] = cb2[tid];
    }
    __syncthreads();

    // ---- image GEMM via mma.sync: warp w owns rows [32w, 32w+32) ----
    float D[2][8][4];
#pragma unroll
    for (int mt = 0; mt < 2; mt++)
#pragma unroll
        for (int nt = 0; nt < 8; nt++)
#pragma unroll
            for (int c = 0; c < 4; c++) D[mt][nt][c] = 0.f;

    {
        const unsigned aRow = 32u*w + (l & 15);
        const unsigned aCol = (unsigned)(l >> 4) * 16u;
        const unsigned bRow = (unsigned)(l & 7);
        const unsigned bCol = (unsigned)((l >> 3) & 1) * 16u;
#pragma unroll
        for (int kc = 0; kc < 3; kc++) {
            unsigned kOff = kc * 32u;
            unsigned ah[2][4], bh[8][2], bl[8][2], al[2][4];
#pragma unroll
            for (int mt = 0; mt < 2; mt++)
                ldsm_x4(ah[mt], smem_base + SM_AHI + (aRow + 16u*mt)*ASTRIDE + kOff + aCol);
#pragma unroll
            for (int nt = 0; nt < 8; nt++)
                ldsm_x2(bh[nt], smem_base + SM_BHI + (bRow + 8u*nt)*ASTRIDE + kOff + bCol);
#pragma unroll
            for (int mt = 0; mt < 2; mt++)
#pragma unroll
                for (int nt = 0; nt < 8; nt++) mma_bf16(D[mt][nt], ah[mt], bh[nt]);
#pragma unroll
            for (int nt = 0; nt < 8; nt++)
                ldsm_x2(bl[nt], smem_base + SM_BLO + (bRow + 8u*nt)*ASTRIDE + kOff + bCol);
#pragma unroll
            for (int mt = 0; mt < 2; mt++)
#pragma unroll
                for (int nt = 0; nt < 8; nt++) mma_bf16(D[mt][nt], ah[mt], bl[nt]);
#pragma unroll
            for (int mt = 0; mt < 2; mt++)
                ldsm_x4(al[mt], smem_base + SM_ALO + (aRow + 16u*mt)*ASTRIDE + kOff + aCol);
#pragma unroll
            for (int mt = 0; mt < 2; mt++)
#pragma unroll
                for (int nt = 0; nt < 8; nt++) mma_bf16(D[mt][nt], al[mt], bh[nt]);
        }
    }

    // ---- fold relu(D + ib1) . iW2 in registers; quad-shfl reduce ----
    // D fragment: lane l, tile (mt,nt): rows 32w+16mt+(l>>2)+{0,8}, cols 8nt+2(l&3)+{0,1}
    ull pvA[4], pvB[4];
#pragma unroll
    for (int s = 0; s < 4; s++) { pvA[s] = 0ull; pvB[s] = 0ull; }
    {
        const float* wI2s = ep + EP_WI2;
        const float* ib1s = ep + EP_IB1;
#pragma unroll
        for (int nt = 0; nt < 8; nt++) {
            int c0 = 8*nt + 2*(l & 3);
            ulonglong2 w0 = *(const ulonglong2*)&wI2s[c0*4];       // w[c0][0..3]
            ulonglong2 w1 = *(const ulonglong2*)&wI2s[(c0+1)*4];   // w[c0+1][0..3]
            float b0 = ib1s[c0], b1 = ib1s[c0+1];
#pragma unroll
            for (int mt = 0; mt < 2; mt++)
#pragma unroll
                for (int bb = 0; bb < 2; bb++) {
                    int slot = 2*mt + bb;
                    float h0 = fmaxf(D[mt][nt][2*bb]   + b0, 0.f);
                    float h1 = fmaxf(D[mt][nt][2*bb+1] + b1, 0.f);
                    ull hh0, hh1; PACK2(hh0, h0, h0); PACK2(hh1, h1, h1);
                    FFMA2(pvA[slot], hh0, w0.x); FFMA2(pvB[slot], hh0, w0.y);
                    FFMA2(pvA[slot], hh1, w1.x); FFMA2(pvB[slot], hh1, w1.y);
                }
        }
#pragma unroll
        for (int s = 0; s < 4; s++) {
            ull t;
            t = __shfl_xor_sync(0xffffffffu, pvA[s], 1); ADD2(pvA[s], pvA[s], t);
            t = __shfl_xor_sync(0xffffffffu, pvA[s], 2); ADD2(pvA[s], pvA[s], t);
            t = __shfl_xor_sync(0xffffffffu, pvB[s], 1); ADD2(pvB[s], pvB[s], t);
            t = __shfl_xor_sync(0xffffffffu, pvB[s], 2); ADD2(pvB[s], pvB[s], t);
        }
    }

    // ---- text MLP1 (R9 FFMA2 path): 128x32, K=16, microtile 8x4 ----
    const int trow = tid >> 3;
    const int tcol = tid & 7;
    const int m0 = trow * 8;
    ull pvT[8][2];
    {
        const int t0 = tcol * 4;
        const float* xt = xRt + m0 * XTS;
        const float* tb1s = ep + EP_TB1;
        ull acc2[8][2];
        ulonglong2 bb = *(const ulonglong2*)&tb1s[t0];
#pragma unroll
        for (int i = 0; i < 8; i++) { acc2[i][0] = bb.x; acc2[i][1] = bb.y; }
#pragma unroll
        for (int k = 0; k < 16; k++) {
            ulonglong2 b01 = *(const ulonglong2*)&wT1s[k*32 + t0];
#pragma unroll
            for (int i = 0; i < 8; i++) {
                float av = xt[i*XTS + k];
                ull aa; PACK2(aa, av, av);
                FFMA2(acc2[i][0], aa, b01.x);
                FFMA2(acc2[i][1], aa, b01.y);
            }
        }
        const float* wT2s = ep + EP_WT2;
#pragma unroll
        for (int i = 0; i < 8; i++) { pvT[i][0] = 0ull; pvT[i][1] = 0ull; }
#pragma unroll
        for (int jj = 0; jj < 2; jj++) {
            int nj0 = t0 + 2*jj;
            ulonglong2 wA = *(const ulonglong2*)&wT2s[nj0*4];
            ulonglong2 wB = *(const ulonglong2*)&wT2s[(nj0+1)*4];
#pragma unroll
            for (int i = 0; i < 8; i++) {
                float h0, h1;
                UNPACK2(h0, h1, acc2[i][jj]);
                h0 = fmaxf(h0, 0.f); h1 = fmaxf(h1, 0.f);
                ull hh0, hh1; PACK2(hh0, h0, h0); PACK2(hh1, h1, h1);
                FFMA2(pvT[i][0], hh0, wA.x); FFMA2(pvT[i][1], hh0, wA.y);
                FFMA2(pvT[i][0], hh1, wB.x); FFMA2(pvT[i][1], hh1, wB.y);
            }
        }
#pragma unroll
        for (int i = 0; i < 8; i++)
#pragma unroll
            for (int n = 0; n < 2; n++) {
                ull v = pvT[i][n], t;
                t = __shfl_xor_sync(0xffffffffu, v, 4); ADD2(v, v, t);
                t = __shfl_xor_sync(0xffffffffu, v, 2); ADD2(v, v, t);
                t = __shfl_xor_sync(0xffffffffu, v, 1); ADD2(v, v, t);
                pvT[i][n] = v;
            }
    }

    __syncthreads();   // all mma reads of A/B done -> TF buffers may alias

    if ((l & 3) == 0) {
#pragma unroll
        for (int s = 0; s < 4; s++) {
            int row = 32*w + 8*s + (l >> 2);
            ulonglong2 v; v.x = pvA[s]; v.y = pvB[s];
            *(ulonglong2*)(smc + SM_TFI + row*16) = v;
        }
    }
    if (tcol == 0) {
#pragma unroll
        for (int i = 0; i < 8; i++) {
            ulonglong2 v; v.x = pvT[i][0]; v.y = pvT[i][1];
            *(ulonglong2*)(smc + SM_TFT + (m0 + i)*16) = v;
        }
    }
    __syncthreads();

    // ---- feats + quantum + classifier: one sample per thread ----
    float fx, fy, fz, fw;
    {
        ulonglong2 ti = *(const ulonglong2*)(smc + SM_TFI + tid*16);
        ulonglong2 tt = *(const ulonglong2*)(smc + SM_TFT + tid*16);
        ulonglong2 bb = *(const ulonglong2*)(ep + EP_B2);
        ull half2p; PACK2(half2p, 0.5f, 0.5f);
        ull sA, sB;
        ADD2(sA, ti.x, tt.x); ADD2(sA, sA, bb.x); MUL2(sA, sA, half2p);
        ADD2(sB, ti.y, tt.y); ADD2(sB, sB, bb.y); MUL2(sB, sB, half2p);
        UNPACK2(fx, fy, sA); UNPACK2(fz, fw, sB);
    }

    const float* Ms  = ep + EP_M;
    const float* cls = ep + EP_CLS;
    float c0, q0s, c1, q1s, c2, q2s, c3, q3s;
    __sincosf(0.5f*fx, &q0s, &c0);
    __sincosf(0.5f*fy, &q1s, &c1);
    __sincosf(0.5f*fz, &q2s, &c2);
    __sincosf(0.5f*fw, &q3s, &c3);

    float p01[4] = {c0*c1, c0*q1s, q0s*c1, q0s*q1s};
    float p23[4] = {c2*c3, c2*q3s, q2s*c3, q2s*q3s};
    ull p23p0, p23p1;
    PACK2(p23p0, p23[0], p23[1]);
    PACK2(p23p1, p23[2], p23[3]);
    ull e2[8];
    float e[16];
#pragma unroll
    for (int a = 0; a < 4; a++) {
        ull pa; PACK2(pa, p01[a], p01[a]);
        MUL2(e2[a*2+0], pa, p23p0);
        MUL2(e2[a*2+1], pa, p23p1);
        UNPACK2(e[a*4+0], e[a*4+1], e2[a*2+0]);
        UNPACK2(e[a*4+2], e[a*4+3], e2[a*2+1]);
    }

    float q = 0.f;
#pragma unroll
    for (int j = 0; j < 16; j++) {
        const ulonglong2* Mr = (const ulonglong2*)&Ms[j*16];
        ulonglong2 m0v = Mr[0], m1v = Mr[1], m2v = Mr[2], m3v = Mr[3];
        ull t2 = 0ull;
        FFMA2(t2, m0v.x, e2[0]); FFMA2(t2, m0v.y, e2[1]);
        FFMA2(t2, m1v.x, e2[2]); FFMA2(t2, m1v.y, e2[3]);
        FFMA2(t2, m2v.x, e2[4]); FFMA2(t2, m2v.y, e2[5]);
        FFMA2(t2, m3v.x, e2[6]); FFMA2(t2, m3v.y, e2[7]);
        float tl, th; UNPACK2(tl, th, t2);
        q = fmaf(e[j], tl + th, q);
    }

    float o0 = cls[64], o1 = cls[65];
#pragma unroll
    for (int m = 0; m < 16; m++) {
        float h = fmaxf(fmaf(q, cls[m], cls[16+m]), 0.f);
        o0 = fmaf(h, cls[32+2*m], o0);
        o1 = fmaf(h, cls[33+2*m], o1);
    }
    float2 res; res.x = o0; res.y = o1;
    ((float2*)out)[base + tid] = res;
}

// ---------------------------------------------------------------------------
extern "C" void kernel_launch(void* const* d_in, const int* in_sizes, int n_in,
                              void* d_out, int out_size) {
    const float* text = (const float*)d_in[0];
    const float* image= (const float*)d_in[1];
    const float* tW1  = (const float*)d_in[2];
    const float* tb1  = (const float*)d_in[3];
    const float* tW2  = (const float*)d_in[4];
    const float* tb2  = (const float*)d_in[5];
    const float* iW1  = (const float*)d_in[6];
    const float* ib1  = (const float*)d_in[7];
    const float* iW2  = (const float*)d_in[8];
    const float* ib2  = (const float*)d_in[9];
    const float* qw   = (const float*)d_in[10];
    const float* cW1  = (const float*)d_in[11];
    const float* cb1  = (const float*)d_in[12];
    const float* cW2  = (const float*)d_in[13];
    const float* cb2  = (const float*)d_in[14];
    float* out = (float*)d_out;

    const int B = in_sizes[0] / 16;
    const int grid = B / 128;

    cudaFuncSetAttribute(qnn_kernel, cudaFuncAttributeMaxDynamicSharedMemorySize, SMEM_BYTES);

    build_M_kernel<<<1, 16>>>(qw);
    qnn_kernel<<<grid, 128, SMEM_BYTES>>>(text, image, tW1, tb1, tW2, tb2,
                                          iW1, ib1, iW2, ib2,
                                          cW1, cb1, cW2, cb2, out);
}

// round 14
// speedup vs baseline: 1.3656x; 1.1337x over previous
#include <cuda_runtime.h>
#include <cstdint>

// ---------------------------------------------------------------------------
// QuantumNeuralNetwork: mma.sync bf16-split GEMMs (image + text) fused fold
//
// <Z0> = e^T M e with M = Re(U' Z0 U) precomputed by build_M_kernel.
//
// R13: text MLP1 moved onto mma.sync as well (128x32x16, 3-term bf16 split,
// 24 mma + ~12 ldsm) replacing the FFMA2 micro-GEMM (~190 L1 wf + ~530
// instr/warp). Text D-fragments share the image fragment row mapping, so the
// relu.W2 folds of BOTH modalities accumulate into one pv register set ->
// single quad-shfl reduce, single smem feats buffer.
// ---------------------------------------------------------------------------

typedef unsigned long long ull;

#define FFMA2(d, a, b) \
    asm("fma.rn.f32x2 %0, %1, %2, %0;" : "+l"(d) : "l"(a), "l"(b))
#define MUL2(d, a, b) \
    asm("mul.rn.f32x2 %0, %1, %2;" : "=l"(d) : "l"(a), "l"(b))
#define ADD2(d, a, b) \
    asm("add.rn.f32x2 %0, %1, %2;" : "=l"(d) : "l"(a), "l"(b))
#define PACK2(out, lo, hi) \
    asm("mov.b64 %0, {%1, %2};" : "=l"(out) : "r"(__float_as_uint(lo)), "r"(__float_as_uint(hi)))
#define UNPACK2(lo, hi, v) do { unsigned _ulo, _uhi; \
    asm("mov.b64 {%0, %1}, %2;" : "=r"(_ulo), "=r"(_uhi) : "l"(v)); \
    lo = __uint_as_float(_ulo); hi = __uint_as_float(_uhi); } while (0)

// ---- smem byte offsets ----
#define SM_AHI   0                      // image A hi: 128 x 112B (48 bf16 + pad)
#define SM_ALO   14336                  // image A lo (TF aliases here post-MMA)
#define SM_BHI   28672                  // image B (iW1^T) hi: 64 x 112B
#define SM_BLO   35840                  // -> 43008
#define SM_TFI   14336                  // alias over ALO: [128] float4 feats sums
#define SM_XHI   43008                  // text A hi: 128 x 48B (16 bf16 + pad)
#define SM_XLO   49152                  // -> 55296
#define SM_YHI   55296                  // text B (tW1^T) hi: 32 x 48B
#define SM_YLO   56832                  // -> 58368
#define SM_EP    58368                  // epilogue consts (floats)
#define EP_WI2   0                      // [64][4]
#define EP_WT2   256                    // [32][4]
#define EP_IB1   384                    // [64]
#define EP_TB1   448                    // [32]
#define EP_B2    480                    // [4] ib2+tb2
#define EP_M     484                    // [16][16]
#define EP_CLS   740                    // cW1[16] cb1[16] cW2[32] cb2[2]
#define EP_FLOATS 808
#define SMEM_BYTES (SM_EP + EP_FLOATS*4)   // 61600

#define ASTRIDE 112   // image tile row stride (bytes)
#define TSTRIDE 48    // text tile row stride (bytes)

__device__ __forceinline__ uint32_t smem_u32(const void* p) {
    uint32_t a;
    asm("{ .reg .u64 t; cvta.to.shared.u64 t, %1; cvt.u32.u64 %0, t; }" : "=r"(a) : "l"(p));
    return a;
}
__device__ __forceinline__ unsigned bf16pair(float lo, float hi) {
    unsigned r; asm("cvt.rn.bf16x2.f32 %0, %1, %2;" : "=r"(r) : "f"(hi), "f"(lo)); return r;
}
__device__ __forceinline__ unsigned short bf16s(float x) {
    unsigned short h; asm("cvt.rn.bf16.f32 %0, %1;" : "=h"(h) : "f"(x)); return h;
}
__device__ __forceinline__ void ldsm_x4(unsigned* r, uint32_t addr) {
    asm volatile("ldmatrix.sync.aligned.m8n8.x4.shared.b16 {%0,%1,%2,%3}, [%4];"
        : "=r"(r[0]), "=r"(r[1]), "=r"(r[2]), "=r"(r[3]) : "r"(addr));
}
__device__ __forceinline__ void ldsm_x2(unsigned* r, uint32_t addr) {
    asm volatile("ldmatrix.sync.aligned.m8n8.x2.shared.b16 {%0,%1}, [%2];"
        : "=r"(r[0]), "=r"(r[1]) : "r"(addr));
}
__device__ __forceinline__ void mma_bf16(float* d, const unsigned* a, const unsigned* b) {
    asm volatile("mma.sync.aligned.m16n8k16.row.col.f32.bf16.bf16.f32 "
        "{%0,%1,%2,%3}, {%4,%5,%6,%7}, {%8,%9}, {%0,%1,%2,%3};"
        : "+f"(d[0]), "+f"(d[1]), "+f"(d[2]), "+f"(d[3])
        : "r"(a[0]), "r"(a[1]), "r"(a[2]), "r"(a[3]), "r"(b[0]), "r"(b[1]));
}

__device__ __align__(16) float g_M[256];

// ---------------------------------------------------------------------------
// Prologue: build M[16][16] = Re(U^dagger Z0 U) from qweights [2][4][3].
// ---------------------------------------------------------------------------
__global__ void build_M_kernel(const float* __restrict__ qw) {
    __shared__ float Ure[16][16], Uim[16][16];
    const int k = threadIdx.x;
    float vr[16], vi[16];
#pragma unroll
    for (int n = 0; n < 16; n++) { vr[n] = (n == k) ? 1.f : 0.f; vi[n] = 0.f; }

    for (int l = 0; l < 2; l++) {
        for (int i = 0; i < 4; i++) {
            float phi = qw[(l*4 + i)*3 + 0];
            float th  = qw[(l*4 + i)*3 + 1];
            float om  = qw[(l*4 + i)*3 + 2];
            float ct = cosf(0.5f*th), st = sinf(0.5f*th);
            float sp, cp, sm, cm;
            sincosf(0.5f*(phi + om), &sp, &cp);
            sincosf(0.5f*(phi - om), &sm, &cm);
            float u00r =  cp*ct, u00i = -sp*ct;
            float u01r = -cm*st, u01i = -sm*st;
            float u10r =  cm*st, u10i = -sm*st;
            float u11r =  cp*ct, u11i =  sp*ct;
            int mask = 1 << (3 - i);
#pragma unroll
            for (int n = 0; n < 16; n++) {
                if (n & mask) continue;
                int n1 = n | mask;
                float r0 = vr[n],  i0 = vi[n];
                float r1 = vr[n1], i1 = vi[n1];
                vr[n]  = u00r*r0 - u00i*i0 + u01r*r1 - u01i*i1;
                vi[n]  = u00r*i0 + u00i*r0 + u01r*i1 + u01i*r1;
                vr[n1] = u10r*r0 - u10i*i0 + u11r*r1 - u11i*i1;
                vi[n1] = u10r*i0 + u10i*r0 + u11r*i1 + u11i*r1;
            }
        }
        for (int i = 0; i < 3; i++) {
            int m1 = 1 << (3 - i), m2 = 1 << (2 - i);
#pragma unroll
            for (int n = 0; n < 16; n++)
                if ((n & m1) && (n & m2)) { vr[n] = -vr[n]; vi[n] = -vi[n]; }
        }
    }
#pragma unroll
    for (int n = 0; n < 16; n++) { Ure[n][k] = vr[n]; Uim[n][k] = vi[n]; }
    __syncthreads();
#pragma unroll
    for (int j = 0; j < 16; j++) {
        float acc = 0.f;
#pragma unroll
        for (int b = 0; b < 16; b++) {
            float z = (b & 8) ? -1.f : 1.f;
            acc += z * (Ure[b][j]*Ure[b][k] + Uim[b][j]*Uim[b][k]);
        }
        g_M[j*16 + k] = acc;
    }
}

// ---------------------------------------------------------------------------
// Main kernel: 128 threads = 128 samples per block.
// ---------------------------------------------------------------------------
__global__ __launch_bounds__(128) void qnn_kernel(
    const float* __restrict__ text, const float* __restrict__ image,
    const float* __restrict__ tW1,  const float* __restrict__ tb1,
    const float* __restrict__ tW2,  const float* __restrict__ tb2,
    const float* __restrict__ iW1,  const float* __restrict__ ib1,
    const float* __restrict__ iW2,  const float* __restrict__ ib2,
    const float* __restrict__ cW1,  const float* __restrict__ cb1,
    const float* __restrict__ cW2,  const float* __restrict__ cb2,
    float* __restrict__ out)
{
    extern __shared__ __align__(1024) char smc[];
    const uint32_t smem_base = smem_u32(smc);
    float* ep = (float*)(smc + SM_EP);

    const int tid = threadIdx.x;
    const int w   = tid >> 5;
    const int l   = tid & 31;
    const size_t base = (size_t)blockIdx.x * 128;

    // ---- stage: convert inputs/weights to bf16 hi/lo tiles ----
    {
        // image A [128][48] -> AHI/ALO, stride 112B
        const float4* ig = (const float4*)(image + base * 48);
#pragma unroll
        for (int it = 0; it < 12; it++) {
            int idx = it*128 + tid;
            float4 v = ig[idx];
            int s  = idx / 12;
            int kq = idx - s*12;
            unsigned off = (unsigned)s*ASTRIDE + 8u*kq;
            unsigned hp0 = bf16pair(v.x, v.y);
            unsigned hp1 = bf16pair(v.z, v.w);
            float r0 = v.x - __uint_as_float(hp0 << 16);
            float r1 = v.y - __uint_as_float(hp0 & 0xffff0000u);
            float r2 = v.z - __uint_as_float(hp1 << 16);
            float r3 = v.w - __uint_as_float(hp1 & 0xffff0000u);
            unsigned lp0 = bf16pair(r0, r1);
            unsigned lp1 = bf16pair(r2, r3);
            *(ull*)(smc + SM_AHI + off) = (ull)hp0 | ((ull)hp1 << 32);
            *(ull*)(smc + SM_ALO + off) = (ull)lp0 | ((ull)lp1 << 32);
        }
        // image B: iW1[48][64] -> [n][k] bf16 hi/lo
#pragma unroll
        for (int it = 0; it < 6; it++) {
            int idx = it*128 + tid;
            float4 v = ((const float4*)iW1)[idx];
            int kk = idx >> 4;
            int n0 = (idx & 15) * 4;
            float wv[4] = {v.x, v.y, v.z, v.w};
#pragma unroll
            for (int j = 0; j < 4; j++) {
                unsigned off = (unsigned)(n0 + j)*ASTRIDE + 2u*kk;
                unsigned short h = bf16s(wv[j]);
                float lo = wv[j] - __uint_as_float(((unsigned)h) << 16);
                *(unsigned short*)(smc + SM_BHI + off) = h;
                *(unsigned short*)(smc + SM_BLO + off) = bf16s(lo);
            }
        }
        // text A [128][16] -> XHI/XLO, stride 48B
        const float4* tg = (const float4*)(text + base * 16);
#pragma unroll
        for (int it = 0; it < 4; it++) {
            int idx = it*128 + tid;
            float4 v = tg[idx];
            int s  = idx >> 2;
            int kq = idx & 3;
            unsigned off = (unsigned)s*TSTRIDE + 8u*kq;
            unsigned hp0 = bf16pair(v.x, v.y);
            unsigned hp1 = bf16pair(v.z, v.w);
            float r0 = v.x - __uint_as_float(hp0 << 16);
            float r1 = v.y - __uint_as_float(hp0 & 0xffff0000u);
            float r2 = v.z - __uint_as_float(hp1 << 16);
            float r3 = v.w - __uint_as_float(hp1 & 0xffff0000u);
            unsigned lp0 = bf16pair(r0, r1);
            unsigned lp1 = bf16pair(r2, r3);
            *(ull*)(smc + SM_XHI + off) = (ull)hp0 | ((ull)hp1 << 32);
            *(ull*)(smc + SM_XLO + off) = (ull)lp0 | ((ull)lp1 << 32);
        }
        // text B: tW1[16][32] -> [n][k] bf16 hi/lo, stride 48B
        {
            int idx = tid;
            float4 v = ((const float4*)tW1)[idx];
            int kk = idx >> 3;
            int n0 = (idx & 7) * 4;
            float wv[4] = {v.x, v.y, v.z, v.w};
#pragma unroll
            for (int j = 0; j < 4; j++) {
                unsigned off = (unsigned)(n0 + j)*TSTRIDE + 2u*kk;
                unsigned short h = bf16s(wv[j]);
                float lo = wv[j] - __uint_as_float(((unsigned)h) << 16);
                *(unsigned short*)(smc + SM_YHI + off) = h;
                *(unsigned short*)(smc + SM_YLO + off) = bf16s(lo);
            }
        }
        // epilogue constants
        if (tid < 64) {
            ((float4*)(ep + EP_WI2))[tid] = ((const float4*)iW2)[tid];
            ep[EP_IB1 + tid] = ib1[tid];
            ((float4*)(ep + EP_M))[tid] = ((const float4*)g_M)[tid];
        }
        if (tid < 32) {
            ((float4*)(ep + EP_WT2))[tid] = ((const float4*)tW2)[tid];
            ep[EP_TB1 + tid] = tb1[tid];
        }
        if (tid < 16) {
            ep[EP_CLS + tid] = cW1[tid];
            ep[EP_CLS + 16 + tid] = cb1[tid];
            ep[EP_CLS + 32 + 2*tid] = cW2[2*tid];
            ep[EP_CLS + 33 + 2*tid] = cW2[2*tid + 1];
        }
        if (tid < 4) ep[EP_B2 + tid] = ib2[tid] + tb2[tid];
        if (tid < 2) ep[EP_CLS + 64 + tid] = cb2[tid];
    }
    __syncthreads();

    const unsigned aRow = 32u*w + (l & 15);
    const unsigned aCol = (unsigned)(l >> 4) * 16u;
    const unsigned bRow = (unsigned)(l & 7);
    const unsigned bCol = (unsigned)((l >> 3) & 1) * 16u;

    ull pvA[4], pvB[4];
#pragma unroll
    for (int s = 0; s < 4; s++) { pvA[s] = 0ull; pvB[s] = 0ull; }

    // ---- image GEMM (mma.sync, 3-term bf16 split) + in-register fold ----
    {
        float D[2][8][4];
#pragma unroll
        for (int mt = 0; mt < 2; mt++)
#pragma unroll
            for (int nt = 0; nt < 8; nt++)
#pragma unroll
                for (int c = 0; c < 4; c++) D[mt][nt][c] = 0.f;

#pragma unroll
        for (int kc = 0; kc < 3; kc++) {
            unsigned kOff = kc * 32u;
            unsigned ah[2][4], bh[8][2], bl[8][2], al[2][4];
#pragma unroll
            for (int mt = 0; mt < 2; mt++)
                ldsm_x4(ah[mt], smem_base + SM_AHI + (aRow + 16u*mt)*ASTRIDE + kOff + aCol);
#pragma unroll
            for (int nt = 0; nt < 8; nt++)
                ldsm_x2(bh[nt], smem_base + SM_BHI + (bRow + 8u*nt)*ASTRIDE + kOff + bCol);
#pragma unroll
            for (int mt = 0; mt < 2; mt++)
#pragma unroll
                for (int nt = 0; nt < 8; nt++) mma_bf16(D[mt][nt], ah[mt], bh[nt]);
#pragma unroll
            for (int nt = 0; nt < 8; nt++)
                ldsm_x2(bl[nt], smem_base + SM_BLO + (bRow + 8u*nt)*ASTRIDE + kOff + bCol);
#pragma unroll
            for (int mt = 0; mt < 2; mt++)
#pragma unroll
                for (int nt = 0; nt < 8; nt++) mma_bf16(D[mt][nt], ah[mt], bl[nt]);
#pragma unroll
            for (int mt = 0; mt < 2; mt++)
                ldsm_x4(al[mt], smem_base + SM_ALO + (aRow + 16u*mt)*ASTRIDE + kOff + aCol);
#pragma unroll
            for (int mt = 0; mt < 2; mt++)
#pragma unroll
                for (int nt = 0; nt < 8; nt++) mma_bf16(D[mt][nt], al[mt], bh[nt]);
        }

        const float* wI2s = ep + EP_WI2;
        const float* ib1s = ep + EP_IB1;
#pragma unroll
        for (int nt = 0; nt < 8; nt++) {
            int c0 = 8*nt + 2*(l & 3);
            ulonglong2 w0 = *(const ulonglong2*)&wI2s[c0*4];
            ulonglong2 w1 = *(const ulonglong2*)&wI2s[(c0+1)*4];
            float b0 = ib1s[c0], b1 = ib1s[c0+1];
#pragma unroll
            for (int mt = 0; mt < 2; mt++)
#pragma unroll
                for (int bb = 0; bb < 2; bb++) {
                    int slot = 2*mt + bb;
                    float h0 = fmaxf(D[mt][nt][2*bb]   + b0, 0.f);
                    float h1 = fmaxf(D[mt][nt][2*bb+1] + b1, 0.f);
                    ull hh0, hh1; PACK2(hh0, h0, h0); PACK2(hh1, h1, h1);
                    FFMA2(pvA[slot], hh0, w0.x); FFMA2(pvB[slot], hh0, w0.y);
                    FFMA2(pvA[slot], hh1, w1.x); FFMA2(pvB[slot], hh1, w1.y);
                }
        }
    }

    // ---- text GEMM (mma.sync, 3-term, single k-chunk) + fold into same pv ----
    {
        float Dt[2][4][4];
#pragma unroll
        for (int mt = 0; mt < 2; mt++)
#pragma unroll
            for (int nt = 0; nt < 4; nt++)
#pragma unroll
                for (int c = 0; c < 4; c++) Dt[mt][nt][c] = 0.f;

        unsigned xh[2][4], xl[2][4], yh[4][2], yl[4][2];
#pragma unroll
        for (int mt = 0; mt < 2; mt++)
            ldsm_x4(xh[mt], smem_base + SM_XHI + (aRow + 16u*mt)*TSTRIDE + aCol);
#pragma unroll
        for (int nt = 0; nt < 4; nt++)
            ldsm_x2(yh[nt], smem_base + SM_YHI + (bRow + 8u*nt)*TSTRIDE + bCol);
#pragma unroll
        for (int mt = 0; mt < 2; mt++)
#pragma unroll
            for (int nt = 0; nt < 4; nt++) mma_bf16(Dt[mt][nt], xh[mt], yh[nt]);
#pragma unroll
        for (int nt = 0; nt < 4; nt++)
            ldsm_x2(yl[nt], smem_base + SM_YLO + (bRow + 8u*nt)*TSTRIDE + bCol);
#pragma unroll
        for (int mt = 0; mt < 2; mt++)
#pragma unroll
            for (int nt = 0; nt < 4; nt++) mma_bf16(Dt[mt][nt], xh[mt], yl[nt]);
#pragma unroll
        for (int mt = 0; mt < 2; mt++)
            ldsm_x4(xl[mt], smem_base + SM_XLO + (aRow + 16u*mt)*TSTRIDE + aCol);
#pragma unroll
        for (int mt = 0; mt < 2; mt++)
#pragma unroll
            for (int nt = 0; nt < 4; nt++) mma_bf16(Dt[mt][nt], xl[mt], yh[nt]);

        const float* wT2s = ep + EP_WT2;
        const float* tb1s = ep + EP_TB1;
#pragma unroll
        for (int nt = 0; nt < 4; nt++) {
            int c0 = 8*nt + 2*(l & 3);
            ulonglong2 w0 = *(const ulonglong2*)&wT2s[c0*4];
            ulonglong2 w1 = *(const ulonglong2*)&wT2s[(c0+1)*4];
            float b0 = tb1s[c0], b1 = tb1s[c0+1];
#pragma unroll
            for (int mt = 0; mt < 2; mt++)
#pragma unroll
                for (int bb = 0; bb < 2; bb++) {
                    int slot = 2*mt + bb;
                    float h0 = fmaxf(Dt[mt][nt][2*bb]   + b0, 0.f);
                    float h1 = fmaxf(Dt[mt][nt][2*bb+1] + b1, 0.f);
                    ull hh0, hh1; PACK2(hh0, h0, h0); PACK2(hh1, h1, h1);
                    FFMA2(pvA[slot], hh0, w0.x); FFMA2(pvB[slot], hh0, w0.y);
                    FFMA2(pvA[slot], hh1, w1.x); FFMA2(pvB[slot], hh1, w1.y);
                }
        }
    }

    // ---- quad-shfl reduce (cols live in lanes l^1, l^2 of each quad) ----
#pragma unroll
    for (int s = 0; s < 4; s++) {
        ull t;
        t = __shfl_xor_sync(0xffffffffu, pvA[s], 1); ADD2(pvA[s], pvA[s], t);
        t = __shfl_xor_sync(0xffffffffu, pvA[s], 2); ADD2(pvA[s], pvA[s], t);
        t = __shfl_xor_sync(0xffffffffu, pvB[s], 1); ADD2(pvB[s], pvB[s], t);
        t = __shfl_xor_sync(0xffffffffu, pvB[s], 2); ADD2(pvB[s], pvB[s], t);
    }

    __syncthreads();   // all mma reads done -> TF buffer may alias ALO

    if ((l & 3) == 0) {
#pragma unroll
        for (int s = 0; s < 4; s++) {
            int row = 32*w + 8*s + (l >> 2);   // s encodes (mt, bb): rows 16mt+8bb+(l>>2)
            ulonglong2 v; v.x = pvA[s]; v.y = pvB[s];
            *(ulonglong2*)(smc + SM_TFI + row*16) = v;
        }
    }
    __syncthreads();

    // ---- feats + quantum + classifier: one sample per thread ----
    float fx, fy, fz, fw;
    {
        ulonglong2 ti = *(const ulonglong2*)(smc + SM_TFI + tid*16);
        ulonglong2 bb = *(const ulonglong2*)(ep + EP_B2);
        ull half2p; PACK2(half2p, 0.5f, 0.5f);
        ull sA, sB;
        ADD2(sA, ti.x, bb.x); MUL2(sA, sA, half2p);
        ADD2(sB, ti.y, bb.y); MUL2(sB, sB, half2p);
        UNPACK2(fx, fy, sA); UNPACK2(fz, fw, sB);
    }

    const float* Ms  = ep + EP_M;
    const float* cls = ep + EP_CLS;
    float c0, q0s, c1, q1s, c2, q2s, c3, q3s;
    __sincosf(0.5f*fx, &q0s, &c0);
    __sincosf(0.5f*fy, &q1s, &c1);
    __sincosf(0.5f*fz, &q2s, &c2);
    __sincosf(0.5f*fw, &q3s, &c3);

    float p01[4] = {c0*c1, c0*q1s, q0s*c1, q0s*q1s};
    float p23[4] = {c2*c3, c2*q3s, q2s*c3, q2s*q3s};
    ull p23p0, p23p1;
    PACK2(p23p0, p23[0], p23[1]);
    PACK2(p23p1, p23[2], p23[3]);
    ull e2[8];
    float e[16];
#pragma unroll
    for (int a = 0; a < 4; a++) {
        ull pa; PACK2(pa, p01[a], p01[a]);
        MUL2(e2[a*2+0], pa, p23p0);
        MUL2(e2[a*2+1], pa, p23p1);
        UNPACK2(e[a*4+0], e[a*4+1], e2[a*2+0]);
        UNPACK2(e[a*4+2], e[a*4+3], e2[a*2+1]);
    }

    float q = 0.f;
#pragma unroll
    for (int j = 0; j < 16; j++) {
        const ulonglong2* Mr = (const ulonglong2*)&Ms[j*16];
        ulonglong2 m0v = Mr[0], m1v = Mr[1], m2v = Mr[2], m3v = Mr[3];
        ull t2 = 0ull;
        FFMA2(t2, m0v.x, e2[0]); FFMA2(t2, m0v.y, e2[1]);
        FFMA2(t2, m1v.x, e2[2]); FFMA2(t2, m1v.y, e2[3]);
        FFMA2(t2, m2v.x, e2[4]); FFMA2(t2, m2v.y, e2[5]);
        FFMA2(t2, m3v.x, e2[6]); FFMA2(t2, m3v.y, e2[7]);
        float tl, th; UNPACK2(tl, th, t2);
        q = fmaf(e[j], tl + th, q);
    }

    float o0 = cls[64], o1 = cls[65];
#pragma unroll
    for (int m = 0; m < 16; m++) {
        float h = fmaxf(fmaf(q, cls[m], cls[16+m]), 0.f);
        o0 = fmaf(h, cls[32+2*m], o0);
        o1 = fmaf(h, cls[33+2*m], o1);
    }
    float2 res; res.x = o0; res.y = o1;
    ((float2*)out)[base + tid] = res;
}

// ---------------------------------------------------------------------------
extern "C" void kernel_launch(void* const* d_in, const int* in_sizes, int n_in,
                              void* d_out, int out_size) {
    const float* text = (const float*)d_in[0];
    const float* image= (const float*)d_in[1];
    const float* tW1  = (const float*)d_in[2];
    const float* tb1  = (const float*)d_in[3];
    const float* tW2  = (const float*)d_in[4];
    const float* tb2  = (const float*)d_in[5];
    const float* iW1  = (const float*)d_in[6];
    const float* ib1  = (const float*)d_in[7];
    const float* iW2  = (const float*)d_in[8];
    const float* ib2  = (const float*)d_in[9];
    const float* qw   = (const float*)d_in[10];
    const float* cW1  = (const float*)d_in[11];
    const float* cb1  = (const float*)d_in[12];
    const float* cW2  = (const float*)d_in[13];
    const float* cb2  = (const float*)d_in[14];
    float* out = (float*)d_out;

    const int B = in_sizes[0] / 16;
    const int grid = B / 128;

    cudaFuncSetAttribute(qnn_kernel, cudaFuncAttributeMaxDynamicSharedMemorySize, SMEM_BYTES);

    build_M_kernel<<<1, 16>>>(qw);
    qnn_kernel<<<grid, 128, SMEM_BYTES>>>(text, image, tW1, tb1, tW2, tb2,
                                          iW1, ib1, iW2, ib2,
                                          cW1, cb1, cW2, cb2, out);
}

// round 15
// speedup vs baseline: 1.5385x; 1.1266x over previous
#include <cuda_runtime.h>
#include <cstdint>

// ---------------------------------------------------------------------------
// QuantumNeuralNetwork: mma.sync bf16-split GEMMs, ldmatrix.trans B operands
//
// <Z0> = e^T M e with M = Re(U' Z0 U) precomputed by build_M_kernel.
//
// R14: B tiles kept in natural [k][n] layout; transpose moved into
// ldmatrix.x2.trans (scatter STS.16 8-way conflicts -> coalesced STS.64:
// ~440 L1 wavefronts/warp removed). hi/lo packed into single widened tiles:
// smem 61.6KB -> 55.5KB -> 4 blocks/SM; __launch_bounds__(128,4) caps regs.
// ---------------------------------------------------------------------------

typedef unsigned long long ull;

#define FFMA2(d, a, b) \
    asm("fma.rn.f32x2 %0, %1, %2, %0;" : "+l"(d) : "l"(a), "l"(b))
#define MUL2(d, a, b) \
    asm("mul.rn.f32x2 %0, %1, %2;" : "=l"(d) : "l"(a), "l"(b))
#define ADD2(d, a, b) \
    asm("add.rn.f32x2 %0, %1, %2;" : "=l"(d) : "l"(a), "l"(b))
#define PACK2(out, lo, hi) \
    asm("mov.b64 %0, {%1, %2};" : "=l"(out) : "r"(__float_as_uint(lo)), "r"(__float_as_uint(hi)))
#define UNPACK2(lo, hi, v) do { unsigned _ulo, _uhi; \
    asm("mov.b64 {%0, %1}, %2;" : "=r"(_ulo), "=r"(_uhi) : "l"(v)); \
    lo = __uint_as_float(_ulo); hi = __uint_as_float(_uhi); } while (0)

// ---- smem layout (bytes). hi/lo packed: lo at +LO offset within each row ----
#define SM_A     0          // image A: 128 rows x 208B  (hi 0-95 | lo 96-191 | pad)
#define ASTR     208
#define A_LO     96
#define SM_B     26624      // image B (iW1 [k][n]): 48 rows x 272B (hi 0-127 | lo 128-255 | pad)
#define BSTR     272
#define B_LO     128
#define SM_X     39680      // text A: 128 rows x 80B (hi 0-31 | lo 32-63 | pad)
#define XSTR     80
#define X_LO     32
#define SM_Y     49920      // text B (tW1 [k][n]): 16 rows x 144B (hi 0-63 | lo 64-127 | pad)
#define YSTR     144
#define Y_LO     64
#define SM_TF    0          // alias over A after MMA: [128] float4
#define SM_EP    52224      // epilogue consts (floats)
#define EP_WI2   0          // [64][4]
#define EP_WT2   256        // [32][4]
#define EP_IB1   384        // [64]
#define EP_TB1   448        // [32]
#define EP_B2    480        // [4] ib2+tb2
#define EP_M     484        // [16][16]
#define EP_CLS   740        // cW1[16] cb1[16] cW2[32] cb2[2]
#define EP_FLOATS 808
#define SMEM_BYTES (SM_EP + EP_FLOATS*4)   // 55456

__device__ __forceinline__ uint32_t smem_u32(const void* p) {
    uint32_t a;
    asm("{ .reg .u64 t; cvta.to.shared.u64 t, %1; cvt.u32.u64 %0, t; }" : "=r"(a) : "l"(p));
    return a;
}
__device__ __forceinline__ unsigned bf16pair(float lo, float hi) {
    unsigned r; asm("cvt.rn.bf16x2.f32 %0, %1, %2;" : "=r"(r) : "f"(hi), "f"(lo)); return r;
}
__device__ __forceinline__ void ldsm_x4(unsigned* r, uint32_t addr) {
    asm volatile("ldmatrix.sync.aligned.m8n8.x4.shared.b16 {%0,%1,%2,%3}, [%4];"
        : "=r"(r[0]), "=r"(r[1]), "=r"(r[2]), "=r"(r[3]) : "r"(addr));
}
__device__ __forceinline__ void ldsm_x2t(unsigned* r, uint32_t addr) {
    asm volatile("ldmatrix.sync.aligned.m8n8.x2.trans.shared.b16 {%0,%1}, [%2];"
        : "=r"(r[0]), "=r"(r[1]) : "r"(addr));
}
__device__ __forceinline__ void mma_bf16(float* d, const unsigned* a, const unsigned* b) {
    asm volatile("mma.sync.aligned.m16n8k16.row.col.f32.bf16.bf16.f32 "
        "{%0,%1,%2,%3}, {%4,%5,%6,%7}, {%8,%9}, {%0,%1,%2,%3};"
        : "+f"(d[0]), "+f"(d[1]), "+f"(d[2]), "+f"(d[3])
        : "r"(a[0]), "r"(a[1]), "r"(a[2]), "r"(a[3]), "r"(b[0]), "r"(b[1]));
}

__device__ __align__(16) float g_M[256];

// ---------------------------------------------------------------------------
// Prologue: build M[16][16] = Re(U^dagger Z0 U) from qweights [2][4][3].
// ---------------------------------------------------------------------------
__global__ void build_M_kernel(const float* __restrict__ qw) {
    __shared__ float Ure[16][16], Uim[16][16];
    const int k = threadIdx.x;
    float vr[16], vi[16];
#pragma unroll
    for (int n = 0; n < 16; n++) { vr[n] = (n == k) ? 1.f : 0.f; vi[n] = 0.f; }

    for (int l = 0; l < 2; l++) {
        for (int i = 0; i < 4; i++) {
            float phi = qw[(l*4 + i)*3 + 0];
            float th  = qw[(l*4 + i)*3 + 1];
            float om  = qw[(l*4 + i)*3 + 2];
            float ct = cosf(0.5f*th), st = sinf(0.5f*th);
            float sp, cp, sm, cm;
            sincosf(0.5f*(phi + om), &sp, &cp);
            sincosf(0.5f*(phi - om), &sm, &cm);
            float u00r =  cp*ct, u00i = -sp*ct;
            float u01r = -cm*st, u01i = -sm*st;
            float u10r =  cm*st, u10i = -sm*st;
            float u11r =  cp*ct, u11i =  sp*ct;
            int mask = 1 << (3 - i);
#pragma unroll
            for (int n = 0; n < 16; n++) {
                if (n & mask) continue;
                int n1 = n | mask;
                float r0 = vr[n],  i0 = vi[n];
                float r1 = vr[n1], i1 = vi[n1];
                vr[n]  = u00r*r0 - u00i*i0 + u01r*r1 - u01i*i1;
                vi[n]  = u00r*i0 + u00i*r0 + u01r*i1 + u01i*r1;
                vr[n1] = u10r*r0 - u10i*i0 + u11r*r1 - u11i*i1;
                vi[n1] = u10r*i0 + u10i*r0 + u11r*i1 + u11i*r1;
            }
        }
        for (int i = 0; i < 3; i++) {
            int m1 = 1 << (3 - i), m2 = 1 << (2 - i);
#pragma unroll
            for (int n = 0; n < 16; n++)
                if ((n & m1) && (n & m2)) { vr[n] = -vr[n]; vi[n] = -vi[n]; }
        }
    }
#pragma unroll
    for (int n = 0; n < 16; n++) { Ure[n][k] = vr[n]; Uim[n][k] = vi[n]; }
    __syncthreads();
#pragma unroll
    for (int j = 0; j < 16; j++) {
        float acc = 0.f;
#pragma unroll
        for (int b = 0; b < 16; b++) {
            float z = (b & 8) ? -1.f : 1.f;
            acc += z * (Ure[b][j]*Ure[b][k] + Uim[b][j]*Uim[b][k]);
        }
        g_M[j*16 + k] = acc;
    }
}

// ---------------------------------------------------------------------------
// Main kernel: 128 threads = 128 samples per block.
// ---------------------------------------------------------------------------
__global__ __launch_bounds__(128, 4) void qnn_kernel(
    const float* __restrict__ text, const float* __restrict__ image,
    const float* __restrict__ tW1,  const float* __restrict__ tb1,
    const float* __restrict__ tW2,  const float* __restrict__ tb2,
    const float* __restrict__ iW1,  const float* __restrict__ ib1,
    const float* __restrict__ iW2,  const float* __restrict__ ib2,
    const float* __restrict__ cW1,  const float* __restrict__ cb1,
    const float* __restrict__ cW2,  const float* __restrict__ cb2,
    float* __restrict__ out)
{
    extern __shared__ __align__(1024) char smc[];
    const uint32_t smem_base = smem_u32(smc);
    float* ep = (float*)(smc + SM_EP);

    const int tid = threadIdx.x;
    const int w   = tid >> 5;
    const int l   = tid & 31;
    const size_t base = (size_t)blockIdx.x * 128;

    // ---- stage: convert inputs/weights to bf16 hi/lo tiles ----
    {
        // image A [128][48] -> A tile rows (hi | lo), stride 208B
        const float4* ig = (const float4*)(image + base * 48);
#pragma unroll
        for (int it = 0; it < 12; it++) {
            int idx = it*128 + tid;
            float4 v = ig[idx];
            int s  = idx / 12;
            int kq = idx - s*12;
            unsigned off = (unsigned)s*ASTR + 8u*kq;
            unsigned hp0 = bf16pair(v.x, v.y);
            unsigned hp1 = bf16pair(v.z, v.w);
            float r0 = v.x - __uint_as_float(hp0 << 16);
            float r1 = v.y - __uint_as_float(hp0 & 0xffff0000u);
            float r2 = v.z - __uint_as_float(hp1 << 16);
            float r3 = v.w - __uint_as_float(hp1 & 0xffff0000u);
            unsigned lp0 = bf16pair(r0, r1);
            unsigned lp1 = bf16pair(r2, r3);
            *(ull*)(smc + SM_A + off)        = (ull)hp0 | ((ull)hp1 << 32);
            *(ull*)(smc + SM_A + A_LO + off) = (ull)lp0 | ((ull)lp1 << 32);
        }
        // image B: iW1[48][64] kept [k][n], coalesced hi/lo stores
#pragma unroll
        for (int it = 0; it < 6; it++) {
            int idx = it*128 + tid;
            float4 v = ((const float4*)iW1)[idx];
            int kk = idx >> 4;
            int n0 = (idx & 15) * 4;
            unsigned off = (unsigned)kk*BSTR + 2u*n0;
            unsigned hp0 = bf16pair(v.x, v.y);
            unsigned hp1 = bf16pair(v.z, v.w);
            float r0 = v.x - __uint_as_float(hp0 << 16);
            float r1 = v.y - __uint_as_float(hp0 & 0xffff0000u);
            float r2 = v.z - __uint_as_float(hp1 << 16);
            float r3 = v.w - __uint_as_float(hp1 & 0xffff0000u);
            unsigned lp0 = bf16pair(r0, r1);
            unsigned lp1 = bf16pair(r2, r3);
            *(ull*)(smc + SM_B + off)        = (ull)hp0 | ((ull)hp1 << 32);
            *(ull*)(smc + SM_B + B_LO + off) = (ull)lp0 | ((ull)lp1 << 32);
        }
        // text A [128][16] -> X tile, stride 80B
        const float4* tg = (const float4*)(text + base * 16);
#pragma unroll
        for (int it = 0; it < 4; it++) {
            int idx = it*128 + tid;
            float4 v = tg[idx];
            int s  = idx >> 2;
            int kq = idx & 3;
            unsigned off = (unsigned)s*XSTR + 8u*kq;
            unsigned hp0 = bf16pair(v.x, v.y);
            unsigned hp1 = bf16pair(v.z, v.w);
            float r0 = v.x - __uint_as_float(hp0 << 16);
            float r1 = v.y - __uint_as_float(hp0 & 0xffff0000u);
            float r2 = v.z - __uint_as_float(hp1 << 16);
            float r3 = v.w - __uint_as_float(hp1 & 0xffff0000u);
            unsigned lp0 = bf16pair(r0, r1);
            unsigned lp1 = bf16pair(r2, r3);
            *(ull*)(smc + SM_X + off)        = (ull)hp0 | ((ull)hp1 << 32);
            *(ull*)(smc + SM_X + X_LO + off) = (ull)lp0 | ((ull)lp1 << 32);
        }
        // text B: tW1[16][32] kept [k][n], stride 144B
        {
            int idx = tid;
            float4 v = ((const float4*)tW1)[idx];
            int kk = idx >> 3;
            int n0 = (idx & 7) * 4;
            unsigned off = (unsigned)kk*YSTR + 2u*n0;
            unsigned hp0 = bf16pair(v.x, v.y);
            unsigned hp1 = bf16pair(v.z, v.w);
            float r0 = v.x - __uint_as_float(hp0 << 16);
            float r1 = v.y - __uint_as_float(hp0 & 0xffff0000u);
            float r2 = v.z - __uint_as_float(hp1 << 16);
            float r3 = v.w - __uint_as_float(hp1 & 0xffff0000u);
            unsigned lp0 = bf16pair(r0, r1);
            unsigned lp1 = bf16pair(r2, r3);
            *(ull*)(smc + SM_Y + off)        = (ull)hp0 | ((ull)hp1 << 32);
            *(ull*)(smc + SM_Y + Y_LO + off) = (ull)lp0 | ((ull)lp1 << 32);
        }
        // epilogue constants
        if (tid < 64) {
            ((float4*)(ep + EP_WI2))[tid] = ((const float4*)iW2)[tid];
            ep[EP_IB1 + tid] = ib1[tid];
            ((float4*)(ep + EP_M))[tid] = ((const float4*)g_M)[tid];
        }
        if (tid < 32) {
            ((float4*)(ep + EP_WT2))[tid] = ((const float4*)tW2)[tid];
            ep[EP_TB1 + tid] = tb1[tid];
        }
        if (tid < 16) {
            ep[EP_CLS + tid] = cW1[tid];
            ep[EP_CLS + 16 + tid] = cb1[tid];
            ep[EP_CLS + 32 + 2*tid] = cW2[2*tid];
            ep[EP_CLS + 33 + 2*tid] = cW2[2*tid + 1];
        }
        if (tid < 4) ep[EP_B2 + tid] = ib2[tid] + tb2[tid];
        if (tid < 2) ep[EP_CLS + 64 + tid] = cb2[tid];
    }
    __syncthreads();

    const unsigned aRow = 32u*w + (l & 15);
    const unsigned aCol = (unsigned)(l >> 4) * 16u;
    const unsigned bKl  = (unsigned)(l & 15);          // k row for trans B loads

    ull pvA[4], pvB[4];
#pragma unroll
    for (int s = 0; s < 4; s++) { pvA[s] = 0ull; pvB[s] = 0ull; }

    // ---- image GEMM (mma.sync, 3-term bf16 split) + in-register fold ----
    {
        float D[2][8][4];
#pragma unroll
        for (int mt = 0; mt < 2; mt++)
#pragma unroll
            for (int nt = 0; nt < 8; nt++)
#pragma unroll
                for (int c = 0; c < 4; c++) D[mt][nt][c] = 0.f;

#pragma unroll
        for (int kc = 0; kc < 3; kc++) {
            unsigned kB = kc * 32u;                    // A col bytes
            uint32_t bRowAddr = smem_base + SM_B + (kc*16u + bKl)*BSTR;
            unsigned ah[2][4], al[2][4], bh[8][2], bl[8][2];
#pragma unroll
            for (int mt = 0; mt < 2; mt++)
                ldsm_x4(ah[mt], smem_base + SM_A + (aRow + 16u*mt)*ASTR + kB + aCol);
#pragma unroll
            for (int nt = 0; nt < 8; nt++)
                ldsm_x2t(bh[nt], bRowAddr + nt*16u);
#pragma unroll
            for (int mt = 0; mt < 2; mt++)
#pragma unroll
                for (int nt = 0; nt < 8; nt++) mma_bf16(D[mt][nt], ah[mt], bh[nt]);
#pragma unroll
            for (int nt = 0; nt < 8; nt++)
                ldsm_x2t(bl[nt], bRowAddr + B_LO + nt*16u);
#pragma unroll
            for (int mt = 0; mt < 2; mt++)
#pragma unroll
                for (int nt = 0; nt < 8; nt++) mma_bf16(D[mt][nt], ah[mt], bl[nt]);
#pragma unroll
            for (int mt = 0; mt < 2; mt++)
                ldsm_x4(al[mt], smem_base + SM_A + A_LO + (aRow + 16u*mt)*ASTR + kB + aCol);
#pragma unroll
            for (int mt = 0; mt < 2; mt++)
#pragma unroll
                for (int nt = 0; nt < 8; nt++) mma_bf16(D[mt][nt], al[mt], bh[nt]);
        }

        const float* wI2s = ep + EP_WI2;
        const float* ib1s = ep + EP_IB1;
#pragma unroll
        for (int nt = 0; nt < 8; nt++) {
            int c0 = 8*nt + 2*(l & 3);
            ulonglong2 w0 = *(const ulonglong2*)&wI2s[c0*4];
            ulonglong2 w1 = *(const ulonglong2*)&wI2s[(c0+1)*4];
            float b0 = ib1s[c0], b1 = ib1s[c0+1];
#pragma unroll
            for (int mt = 0; mt < 2; mt++)
#pragma unroll
                for (int bb = 0; bb < 2; bb++) {
                    int slot = 2*mt + bb;
                    float h0 = fmaxf(D[mt][nt][2*bb]   + b0, 0.f);
                    float h1 = fmaxf(D[mt][nt][2*bb+1] + b1, 0.f);
                    ull hh0, hh1; PACK2(hh0, h0, h0); PACK2(hh1, h1, h1);
                    FFMA2(pvA[slot], hh0, w0.x); FFMA2(pvB[slot], hh0, w0.y);
                    FFMA2(pvA[slot], hh1, w1.x); FFMA2(pvB[slot], hh1, w1.y);
                }
        }
    }

    // ---- text GEMM (mma.sync, 3-term, single k-chunk) + fold into same pv ----
    {
        float Dt[2][4][4];
#pragma unroll
        for (int mt = 0; mt < 2; mt++)
#pragma unroll
            for (int nt = 0; nt < 4; nt++)
#pragma unroll
                for (int c = 0; c < 4; c++) Dt[mt][nt][c] = 0.f;

        uint32_t yRowAddr = smem_base + SM_Y + bKl*YSTR;
        unsigned xh[2][4], xl[2][4], yh[4][2], yl[4][2];
#pragma unroll
        for (int mt = 0; mt < 2; mt++)
            ldsm_x4(xh[mt], smem_base + SM_X + (aRow + 16u*mt)*XSTR + aCol);
#pragma unroll
        for (int nt = 0; nt < 4; nt++)
            ldsm_x2t(yh[nt], yRowAddr + nt*16u);
#pragma unroll
        for (int mt = 0; mt < 2; mt++)
#pragma unroll
            for (int nt = 0; nt < 4; nt++) mma_bf16(Dt[mt][nt], xh[mt], yh[nt]);
#pragma unroll
        for (int nt = 0; nt < 4; nt++)
            ldsm_x2t(yl[nt], yRowAddr + Y_LO + nt*16u);
#pragma unroll
        for (int mt = 0; mt < 2; mt++)
#pragma unroll
            for (int nt = 0; nt < 4; nt++) mma_bf16(Dt[mt][nt], xh[mt], yl[nt]);
#pragma unroll
        for (int mt = 0; mt < 2; mt++)
            ldsm_x4(xl[mt], smem_base + SM_X + X_LO + (aRow + 16u*mt)*XSTR + aCol);
#pragma unroll
        for (int mt = 0; mt < 2; mt++)
#pragma unroll
            for (int nt = 0; nt < 4; nt++) mma_bf16(Dt[mt][nt], xl[mt], yh[nt]);

        const float* wT2s = ep + EP_WT2;
        const float* tb1s = ep + EP_TB1;
#pragma unroll
        for (int nt = 0; nt < 4; nt++) {
            int c0 = 8*nt + 2*(l & 3);
            ulonglong2 w0 = *(const ulonglong2*)&wT2s[c0*4];
            ulonglong2 w1 = *(const ulonglong2*)&wT2s[(c0+1)*4];
            float b0 = tb1s[c0], b1 = tb1s[c0+1];
#pragma unroll
            for (int mt = 0; mt < 2; mt++)
#pragma unroll
                for (int bb = 0; bb < 2; bb++) {
                    int slot = 2*mt + bb;
                    float h0 = fmaxf(Dt[mt][nt][2*bb]   + b0, 0.f);
                    float h1 = fmaxf(Dt[mt][nt][2*bb+1] + b1, 0.f);
                    ull hh0, hh1; PACK2(hh0, h0, h0); PACK2(hh1, h1, h1);
                    FFMA2(pvA[slot], hh0, w0.x); FFMA2(pvB[slot], hh0, w0.y);
                    FFMA2(pvA[slot], hh1, w1.x); FFMA2(pvB[slot], hh1, w1.y);
                }
        }
    }

    // ---- quad-shfl reduce (cols live in lanes l^1, l^2 of each quad) ----
#pragma unroll
    for (int s = 0; s < 4; s++) {
        ull t;
        t = __shfl_xor_sync(0xffffffffu, pvA[s], 1); ADD2(pvA[s], pvA[s], t);
        t = __shfl_xor_sync(0xffffffffu, pvA[s], 2); ADD2(pvA[s], pvA[s], t);
        t = __shfl_xor_sync(0xffffffffu, pvB[s], 1); ADD2(pvB[s], pvB[s], t);
        t = __shfl_xor_sync(0xffffffffu, pvB[s], 2); ADD2(pvB[s], pvB[s], t);
    }

    __syncthreads();   // all mma reads done -> TF buffer may alias A

    if ((l & 3) == 0) {
#pragma unroll
        for (int s = 0; s < 4; s++) {
            int row = 32*w + 8*s + (l >> 2);   // s encodes (mt, bb)
            ulonglong2 v; v.x = pvA[s]; v.y = pvB[s];
            *(ulonglong2*)(smc + SM_TF + row*16) = v;
        }
    }
    __syncthreads();

    // ---- feats + quantum + classifier: one sample per thread ----
    float fx, fy, fz, fw;
    {
        ulonglong2 ti = *(const ulonglong2*)(smc + SM_TF + tid*16);
        ulonglong2 bb = *(const ulonglong2*)(ep + EP_B2);
        ull half2p; PACK2(half2p, 0.5f, 0.5f);
        ull sA, sB;
        ADD2(sA, ti.x, bb.x); MUL2(sA, sA, half2p);
        ADD2(sB, ti.y, bb.y); MUL2(sB, sB, half2p);
        UNPACK2(fx, fy, sA); UNPACK2(fz, fw, sB);
    }

    const float* Ms  = ep + EP_M;
    const float* cls = ep + EP_CLS;
    float c0, q0s, c1, q1s, c2, q2s, c3, q3s;
    __sincosf(0.5f*fx, &q0s, &c0);
    __sincosf(0.5f*fy, &q1s, &c1);
    __sincosf(0.5f*fz, &q2s, &c2);
    __sincosf(0.5f*fw, &q3s, &c3);

    float p01[4] = {c0*c1, c0*q1s, q0s*c1, q0s*q1s};
    float p23[4] = {c2*c3, c2*q3s, q2s*c3, q2s*q3s};
    ull p23p0, p23p1;
    PACK2(p23p0, p23[0], p23[1]);
    PACK2(p23p1, p23[2], p23[3]);
    ull e2[8];
    float e[16];
#pragma unroll
    for (int a = 0; a < 4; a++) {
        ull pa; PACK2(pa, p01[a], p01[a]);
        MUL2(e2[a*2+0], pa, p23p0);
        MUL2(e2[a*2+1], pa, p23p1);
        UNPACK2(e[a*4+0], e[a*4+1], e2[a*2+0]);
        UNPACK2(e[a*4+2], e[a*4+3], e2[a*2+1]);
    }

    float q = 0.f;
#pragma unroll
    for (int j = 0; j < 16; j++) {
        const ulonglong2* Mr = (const ulonglong2*)&Ms[j*16];
        ulonglong2 m0v = Mr[0], m1v = Mr[1], m2v = Mr[2], m3v = Mr[3];
        ull t2 = 0ull;
        FFMA2(t2, m0v.x, e2[0]); FFMA2(t2, m0v.y, e2[1]);
        FFMA2(t2, m1v.x, e2[2]); FFMA2(t2, m1v.y, e2[3]);
        FFMA2(t2, m2v.x, e2[4]); FFMA2(t2, m2v.y, e2[5]);
        FFMA2(t2, m3v.x, e2[6]); FFMA2(t2, m3v.y, e2[7]);
        float tl, th; UNPACK2(tl, th, t2);
        q = fmaf(e[j], tl + th, q);
    }

    float o0 = cls[64], o1 = cls[65];
#pragma unroll
    for (int m = 0; m < 16; m++) {
        float h = fmaxf(fmaf(q, cls[m], cls[16+m]), 0.f);
        o0 = fmaf(h, cls[32+2*m], o0);
        o1 = fmaf(h, cls[33+2*m], o1);
    }
    float2 res; res.x = o0; res.y = o1;
    ((float2*)out)[base + tid] = res;
}

// ---------------------------------------------------------------------------
extern "C" void kernel_launch(void* const* d_in, const int* in_sizes, int n_in,
                              void* d_out, int out_size) {
    const float* text = (const float*)d_in[0];
    const float* image= (const float*)d_in[1];
    const float* tW1  = (const float*)d_in[2];
    const float* tb1  = (const float*)d_in[3];
    const float* tW2  = (const float*)d_in[4];
    const float* tb2  = (const float*)d_in[5];
    const float* iW1  = (const float*)d_in[6];
    const float* ib1  = (const float*)d_in[7];
    const float* iW2  = (const float*)d_in[8];
    const float* ib2  = (const float*)d_in[9];
    const float* qw   = (const float*)d_in[10];
    const float* cW1  = (const float*)d_in[11];
    const float* cb1  = (const float*)d_in[12];
    const float* cW2  = (const float*)d_in[13];
    const float* cb2  = (const float*)d_in[14];
    float* out = (float*)d_out;

    const int B = in_sizes[0] / 16;
    const int grid = B / 128;

    cudaFuncSetAttribute(qnn_kernel, cudaFuncAttributeMaxDynamicSharedMemorySize, SMEM_BYTES);

    build_M_kernel<<<1, 16>>>(qw);
    qnn_kernel<<<grid, 128, SMEM_BYTES>>>(text, image, tW1, tb1, tW2, tb2,
                                          iW1, ib1, iW2, ib2,
                                          cW1, cb1, cW2, cb2, out);
}